// round 14
// baseline (speedup 1.0000x reference)
#include <cuda_runtime.h>
#include <cuda_bf16.h>
#include <math.h>
#include <stdint.h>

#define B_  4
#define T_  2048
#define C_  672
#define H_  14
#define D_  48
#define C3_ 2016
#define M_  (B_*T_)    // 8192
#define BHT (B_*H_*T_) // 114688
#define BH_ (B_*H_)    // 56
#define NSLOT 68       // 17 col-tiles x 4 wn-warps

// ---------------- scratch ----------------
__device__ __nv_bfloat16 g_xb [(size_t)M_*C_];
__device__ __nv_bfloat16 g_wat[(size_t)C3_*C_];    // w_attn^T
__device__ __nv_bfloat16 g_wpt[(size_t)C_*C_];     // w_proj^T
__device__ __nv_bfloat16 g_qkv[(size_t)M_*C3_];
__device__ __nv_bfloat16 g_vt [(size_t)BH_*D_*T_]; // V^T per head [bh][48][2048]
__device__ __nv_bfloat16 g_y  [(size_t)M_*C_];
__device__ __nv_bfloat16 g_s  [(size_t)BHT*T_];    // logits -> e (in place)
__device__ float         g_lb [(size_t)BHT];
__device__ float         g_tmax[(size_t)BHT*NSLOT]; // per-(row, ct, wn) tile max
__device__ int g_isbf16[3];

__device__ __forceinline__ float rbf(float v) {
    return __bfloat162float(__float2bfloat16(v));
}

__device__ __forceinline__ void mma16816(float c[4],
        uint32_t a0, uint32_t a1, uint32_t a2, uint32_t a3,
        uint32_t b0, uint32_t b1) {
    asm volatile(
        "mma.sync.aligned.m16n8k16.row.col.f32.bf16.bf16.f32 "
        "{%0,%1,%2,%3}, {%4,%5,%6,%7}, {%8,%9}, {%0,%1,%2,%3};\n"
        : "+f"(c[0]), "+f"(c[1]), "+f"(c[2]), "+f"(c[3])
        : "r"(a0), "r"(a1), "r"(a2), "r"(a3), "r"(b0), "r"(b1));
}

__device__ __forceinline__ void ldsm_x4(uint32_t r[4], const __nv_bfloat16* p) {
    uint32_t addr = (uint32_t)__cvta_generic_to_shared(p);
    asm volatile("ldmatrix.sync.aligned.m8n8.x4.shared.b16 {%0,%1,%2,%3}, [%4];"
                 : "=r"(r[0]), "=r"(r[1]), "=r"(r[2]), "=r"(r[3]) : "r"(addr));
}

// ---------------- input dtype detection (one launch, 3 blocks) --------------
__global__ void detect_dtype3(const void* b0, const void* b1, const void* b2) {
    __shared__ int cnt;
    if (threadIdx.x == 0) cnt = 0;
    __syncthreads();
    const void* bufs[3] = {b0, b1, b2};
    const __nv_bfloat16* hb = (const __nv_bfloat16*)bufs[blockIdx.x];
    int local = 0;
    for (int i = threadIdx.x; i < 4096; i += 256) {
        float v = fabsf(__bfloat162float(hb[i]));
        if (isfinite(v) && v > 1e-5f && v < 1e3f) local++;
    }
    atomicAdd(&cnt, local);
    __syncthreads();
    if (threadIdx.x == 0) g_isbf16[blockIdx.x] = (cnt > 3072);
}

__global__ void cast_input4(const void* src, __nv_bfloat16* dst, int n4, int which) {
    int i = blockIdx.x * blockDim.x + threadIdx.x;
    if (i >= n4) return;
    if (g_isbf16[which]) {
        reinterpret_cast<uint2*>(dst)[i] = reinterpret_cast<const uint2*>(src)[i];
    } else {
        float4 v = reinterpret_cast<const float4*>(src)[i];
        union { __nv_bfloat16 h[4]; uint2 u; } pk;
        pk.h[0] = __float2bfloat16(v.x);
        pk.h[1] = __float2bfloat16(v.y);
        pk.h[2] = __float2bfloat16(v.z);
        pk.h[3] = __float2bfloat16(v.w);
        reinterpret_cast<uint2*>(dst)[i] = pk.u;
    }
}

// ---------------- transpose + cast: src [R][C] (f32 or bf16) -> dst [C][R] bf16
__global__ void transpose_cast(const void* src, __nv_bfloat16* dst,
                               int R, int C, int which) {
    __shared__ __nv_bfloat16 tile[32][33];
    const bool isb = g_isbf16[which] != 0;
    int x = blockIdx.x * 32 + threadIdx.x;
#pragma unroll
    for (int j = 0; j < 4; j++) {
        int y = blockIdx.y * 32 + threadIdx.y + j * 8;
        if (y < R && x < C) {
            __nv_bfloat16 v = isb
                ? ((const __nv_bfloat16*)src)[(size_t)y * C + x]
                : __float2bfloat16(((const float*)src)[(size_t)y * C + x]);
            tile[threadIdx.y + j * 8][threadIdx.x] = v;
        }
    }
    __syncthreads();
    int tx = blockIdx.y * 32 + threadIdx.x;
#pragma unroll
    for (int j = 0; j < 4; j++) {
        int ty = blockIdx.x * 32 + threadIdx.y + j * 8;
        if (ty < C && tx < R) dst[(size_t)ty * R + tx] = tile[threadIdx.x][threadIdx.y + j * 8];
    }
}

// ---------------- HMMA GEMM: C = A[M][K] * Bt[N][K]^T ----------------
__device__ __forceinline__ uint4 ldg_or_zero(const __nv_bfloat16* p, bool valid) {
    uint4 v = make_uint4(0u, 0u, 0u, 0u);
    if (valid) v = *reinterpret_cast<const uint4*>(p);
    return v;
}

template<int EPI>
__global__ __launch_bounds__(256)
void gemm_hmma(const __nv_bfloat16* __restrict__ A,
               const __nv_bfloat16* __restrict__ Bt,
               void* __restrict__ Cout,
               int M, int N, int K) {
    const int PITCH = 40;
    __shared__ __nv_bfloat16 As[128 * PITCH];
    __shared__ __nv_bfloat16 Bs[128 * PITCH];

    const int tid = threadIdx.x, lane = tid & 31, wid = tid >> 5;
    const int wm = wid >> 2, wn = wid & 3;
    const int rowC = blockIdx.y * 128;
    const int colC = blockIdx.x * 128;

    const int srow = tid >> 1;
    const int sseg = (tid & 1) * 16;
    const __nv_bfloat16* Ag = A  + (size_t)(rowC + srow) * K + sseg;
    const bool bvalid = (colC + srow) < N;
    const __nv_bfloat16* Bg = Bt + (size_t)(colC + srow) * K + sseg;

    float acc[4][4][4];
#pragma unroll
    for (int mt = 0; mt < 4; mt++)
#pragma unroll
        for (int nt = 0; nt < 4; nt++)
#pragma unroll
            for (int r = 0; r < 4; r++) acc[mt][nt][r] = 0.f;

    const int nit = K / 32;
    uint4 sa0 = *reinterpret_cast<const uint4*>(Ag);
    uint4 sa1 = *reinterpret_cast<const uint4*>(Ag + 8);
    uint4 sb0 = ldg_or_zero(Bg, bvalid);
    uint4 sb1 = ldg_or_zero(Bg + 8, bvalid);

    *reinterpret_cast<uint4*>(As + srow * PITCH + sseg)     = sa0;
    *reinterpret_cast<uint4*>(As + srow * PITCH + sseg + 8) = sa1;
    *reinterpret_cast<uint4*>(Bs + srow * PITCH + sseg)     = sb0;
    *reinterpret_cast<uint4*>(Bs + srow * PITCH + sseg + 8) = sb1;
    __syncthreads();

    const int aRow = lane & 15, aKo = (lane >> 4) * 8;
    const int bRow = (lane & 7) + (lane >> 4) * 8;
    const int bKo  = ((lane >> 3) & 1) * 8;

    for (int it = 0; it < nit; it++) {
        if (it + 1 < nit) {
            const __nv_bfloat16* Ag2 = Ag + (it + 1) * 32;
            const __nv_bfloat16* Bg2 = Bg + (it + 1) * 32;
            sa0 = *reinterpret_cast<const uint4*>(Ag2);
            sa1 = *reinterpret_cast<const uint4*>(Ag2 + 8);
            sb0 = ldg_or_zero(Bg2, bvalid);
            sb1 = ldg_or_zero(Bg2 + 8, bvalid);
        }
#pragma unroll
        for (int ks = 0; ks < 2; ks++) {
            const int kb0 = ks * 16;
            uint32_t af[4][4];
#pragma unroll
            for (int mt = 0; mt < 4; mt++)
                ldsm_x4(af[mt], As + (wm * 64 + mt * 16 + aRow) * PITCH + kb0 + aKo);
            uint32_t bfr[4][2];
#pragma unroll
            for (int np = 0; np < 2; np++) {
                uint32_t bq[4];
                ldsm_x4(bq, Bs + (wn * 32 + np * 16 + bRow) * PITCH + kb0 + bKo);
                bfr[np * 2][0] = bq[0]; bfr[np * 2][1] = bq[1];
                bfr[np * 2 + 1][0] = bq[2]; bfr[np * 2 + 1][1] = bq[3];
            }
#pragma unroll
            for (int mt = 0; mt < 4; mt++)
#pragma unroll
                for (int nt = 0; nt < 4; nt++)
                    mma16816(acc[mt][nt], af[mt][0], af[mt][1], af[mt][2], af[mt][3],
                             bfr[nt][0], bfr[nt][1]);
        }
        if (it + 1 < nit) {
            __syncthreads();
            *reinterpret_cast<uint4*>(As + srow * PITCH + sseg)     = sa0;
            *reinterpret_cast<uint4*>(As + srow * PITCH + sseg + 8) = sa1;
            *reinterpret_cast<uint4*>(Bs + srow * PITCH + sseg)     = sb0;
            *reinterpret_cast<uint4*>(Bs + srow * PITCH + sseg + 8) = sb1;
            __syncthreads();
        }
    }

#pragma unroll
    for (int mt = 0; mt < 4; mt++) {
        int r0 = rowC + wm * 64 + mt * 16 + (lane >> 2);
#pragma unroll
        for (int nt = 0; nt < 4; nt++) {
            int c0 = colC + wn * 32 + nt * 8 + (lane & 3) * 2;
            if (c0 >= N) continue;
            if (EPI == 0) {
                __nv_bfloat16* Cb = (__nv_bfloat16*)Cout;
                __nv_bfloat162 p0, p1;
                p0.x = __float2bfloat16(acc[mt][nt][0]);
                p0.y = __float2bfloat16(acc[mt][nt][1]);
                p1.x = __float2bfloat16(acc[mt][nt][2]);
                p1.y = __float2bfloat16(acc[mt][nt][3]);
                *reinterpret_cast<__nv_bfloat162*>(Cb + (size_t)r0 * N + c0)       = p0;
                *reinterpret_cast<__nv_bfloat162*>(Cb + (size_t)(r0 + 8) * N + c0) = p1;
            } else {
                float* Cf = (float*)Cout;
                float2 q0 = make_float2(rbf(acc[mt][nt][0]), rbf(acc[mt][nt][1]));
                float2 q1 = make_float2(rbf(acc[mt][nt][2]), rbf(acc[mt][nt][3]));
                *reinterpret_cast<float2*>(Cf + (size_t)r0 * N + c0)       = q0;
                *reinterpret_cast<float2*>(Cf + (size_t)(r0 + 8) * N + c0) = q1;
            }
        }
    }
}

// ---------------- V^T per head: g_vt[bh][d][t] ----------------
__global__ __launch_bounds__(256)
void vt_kernel() {
    int tt = blockIdx.x, bh = blockIdx.y;
    int b = bh / H_, h = bh % H_;
    __shared__ __nv_bfloat16 tile[64][56];
    for (int i = threadIdx.x; i < 64 * 6; i += 256) {
        int r = i / 6, s = (i % 6) * 8;
        *reinterpret_cast<uint4*>(&tile[r][s]) =
            *reinterpret_cast<const uint4*>(
                &g_qkv[(size_t)(b * T_ + tt * 64 + r) * C3_ + 2 * C_ + h * D_ + s]);
    }
    __syncthreads();
    for (int i = threadIdx.x; i < D_ * 64; i += 256) {
        int d = i / 64, t = i % 64;
        g_vt[((size_t)bh * D_ + d) * T_ + tt * 64 + t] = tile[t][d];
    }
}

// ---------------- QK logits via HMMA + contention-free row tile-max ---------
__global__ __launch_bounds__(256)
void qk_hmma() {
    int ct = blockIdx.x, rt = blockIdx.y, bh = blockIdx.z;
    if (ct > rt + 1) return;
    int b = bh / H_, h = bh % H_;
    const int PITCH = 56;
    __shared__ __nv_bfloat16 Qs[128 * PITCH];
    __shared__ __nv_bfloat16 Ks[128 * PITCH];

    const int tid = threadIdx.x, lane = tid & 31, wid = tid >> 5;
    const int wm = wid >> 2, wn = wid & 3;

    const __nv_bfloat16* Qg = g_qkv + (size_t)(b * T_ + rt * 128) * C3_ + h * D_;
    const __nv_bfloat16* Kg = g_qkv + (size_t)(b * T_ + ct * 128) * C3_ + C_ + h * D_;
    for (int c = tid; c < 768; c += 256) {
        int r = c / 6, s = (c % 6) * 8;
        *reinterpret_cast<uint4*>(Qs + r * PITCH + s) =
            *reinterpret_cast<const uint4*>(Qg + (size_t)r * C3_ + s);
        *reinterpret_cast<uint4*>(Ks + r * PITCH + s) =
            *reinterpret_cast<const uint4*>(Kg + (size_t)r * C3_ + s);
    }
    __syncthreads();

    float acc[4][4][4];
#pragma unroll
    for (int mt = 0; mt < 4; mt++)
#pragma unroll
        for (int nt = 0; nt < 4; nt++)
#pragma unroll
            for (int r = 0; r < 4; r++) acc[mt][nt][r] = 0.f;

    const int aRow = lane & 15, aKo = (lane >> 4) * 8;
    const int bRow = (lane & 7) + (lane >> 4) * 8;
    const int bKo  = ((lane >> 3) & 1) * 8;

#pragma unroll
    for (int ks = 0; ks < 3; ks++) {
        const int kb0 = ks * 16;
        uint32_t af[4][4];
#pragma unroll
        for (int mt = 0; mt < 4; mt++)
            ldsm_x4(af[mt], Qs + (wm * 64 + mt * 16 + aRow) * PITCH + kb0 + aKo);
        uint32_t bfr[4][2];
#pragma unroll
        for (int np = 0; np < 2; np++) {
            uint32_t bq[4];
            ldsm_x4(bq, Ks + (wn * 32 + np * 16 + bRow) * PITCH + kb0 + bKo);
            bfr[np * 2][0] = bq[0]; bfr[np * 2][1] = bq[1];
            bfr[np * 2 + 1][0] = bq[2]; bfr[np * 2 + 1][1] = bq[3];
        }
#pragma unroll
        for (int mt = 0; mt < 4; mt++)
#pragma unroll
            for (int nt = 0; nt < 4; nt++)
                mma16816(acc[mt][nt], af[mt][0], af[mt][1], af[mt][2], af[mt][3],
                         bfr[nt][0], bfr[nt][1]);
    }

    const float scale = rbf(0.14433756729740643f);
    const __nv_bfloat16 NEGINF = __float2bfloat16(-INFINITY);
    float rowmax[4][2];
#pragma unroll
    for (int mt = 0; mt < 4; mt++) { rowmax[mt][0] = -INFINITY; rowmax[mt][1] = -INFINITY; }

#pragma unroll
    for (int mt = 0; mt < 4; mt++) {
        int r0 = rt * 128 + wm * 64 + mt * 16 + (lane >> 2);
#pragma unroll
        for (int nt = 0; nt < 4; nt++) {
            int c0 = ct * 128 + wn * 32 + nt * 8 + (lane & 3) * 2;
#pragma unroll
            for (int half = 0; half < 2; half++) {
                int rr = r0 + half * 8;
                float rq = rbf((float)rr);
                __nv_bfloat162 pk;
                float v0 = acc[mt][nt][half * 2 + 0];
                float v1 = acc[mt][nt][half * 2 + 1];
                pk.x = (rbf((float)(c0    )) <= rq) ? __float2bfloat16(rbf(v0) * scale) : NEGINF;
                pk.y = (rbf((float)(c0 + 1)) <= rq) ? __float2bfloat16(rbf(v1) * scale) : NEGINF;
                *reinterpret_cast<__nv_bfloat162*>(
                    &g_s[((size_t)bh * T_ + rr) * T_ + c0]) = pk;
                rowmax[mt][half] = fmaxf(rowmax[mt][half],
                    fmaxf(__bfloat162float(pk.x), __bfloat162float(pk.y)));
            }
        }
    }

    // quad-reduce row max (lanes with same lane>>2 hold same row, diff cols),
    // then ONE writer per (row, ct, wn) slot — no contention, no init needed.
#pragma unroll
    for (int mt = 0; mt < 4; mt++)
#pragma unroll
        for (int half = 0; half < 2; half++) {
            float v = rowmax[mt][half];
            v = fmaxf(v, __shfl_xor_sync(0xffffffffu, v, 1));
            v = fmaxf(v, __shfl_xor_sync(0xffffffffu, v, 2));
            if ((lane & 3) == 0) {
                int rr = rt * 128 + wm * 64 + mt * 16 + (lane >> 2) + half * 8;
                g_tmax[((size_t)bh * T_ + rr) * NSLOT + ct * 4 + wn] = v;
            }
        }
}

// ---------------- softmax: ONE sweep; s -> e in place; lb out ---------------
__global__ __launch_bounds__(128)
void softmax_es() {
    const int wid = threadIdx.x >> 5, lane = threadIdx.x & 31;
    const int r = blockIdx.x * 4 + wid;        // row over BHT
    const int t = r & (T_ - 1);
    const int qt = t >> 7;
    const int ncov = min(2 * qt + 3, 32);      // covered 64-key tiles
    const int nvec = ncov * 8;                 // uint4 count

    // global row max from per-tile maxima (exact: same value set as a sweep)
    const int nslots = (qt + 2) * 4;           // ct in [0, qt+1], 4 wn each
    float m = -INFINITY;
    for (int i = lane; i < nslots; i += 32)
        m = fmaxf(m, g_tmax[(size_t)r * NSLOT + i]);
#pragma unroll
    for (int off = 16; off; off >>= 1)
        m = fmaxf(m, __shfl_xor_sync(0xffffffffu, m, off));

    uint4* sv = reinterpret_cast<uint4*>(g_s + (size_t)r * T_);
    union U8 { uint4 u; __nv_bfloat16 h[8]; };

    float l = 0.f;
    for (int i = lane; i < nvec; i += 32) {
        U8 pk; pk.u = sv[i];
        U8 eo;
#pragma unroll
        for (int j = 0; j < 8; j++) {
            float s = __bfloat162float(pk.h[j]);
            float e = rbf(__expf(rbf(s - m)));
            l += e;
            eo.h[j] = __float2bfloat16(e);
        }
        sv[i] = eo.u;
    }
#pragma unroll
    for (int off = 16; off; off >>= 1)
        l += __shfl_xor_sync(0xffffffffu, l, off);

    if (lane == 0) g_lb[r] = rbf(l);
}

// ---------------- PV via HMMA: O[128 x 48] = P * V per (qt, bh) -------------
__global__ __launch_bounds__(128)
void pv_hmma() {
    const int qt = blockIdx.x, bh = blockIdx.y;
    const int b = bh / H_, h = bh % H_;
    const int PITCH = 72;                 // 64 k + pad
    __shared__ __nv_bfloat16 Ps[128 * PITCH];
    __shared__ __nv_bfloat16 Vs[48 * PITCH];

    const int tid = threadIdx.x, lane = tid & 31, wid = tid >> 5;
    const int rowg = qt * 128 + tid;
    const float inv = 1.0f / g_lb[(size_t)bh * T_ + rowg];
    const __nv_bfloat16* erow = g_s + ((size_t)bh * T_ + rowg) * T_;

    float acc[2][6][4];
#pragma unroll
    for (int mt = 0; mt < 2; mt++)
#pragma unroll
        for (int nt = 0; nt < 6; nt++)
#pragma unroll
            for (int q = 0; q < 4; q++) acc[mt][nt][q] = 0.f;

    const int ncov = min(2 * qt + 3, 32);   // 64-key chunks (= softmax coverage)
    union U8 { uint4 u; __nv_bfloat16 h[8]; };

    const int aRow = lane & 15, aKo = (lane >> 4) * 8;
    const int bRow = (lane & 7) + (lane >> 4) * 8;
    const int bKo  = ((lane >> 3) & 1) * 8;

    for (int it = 0; it < ncov; it++) {
        const int k0 = it * 64;
#pragma unroll
        for (int j = 0; j < 8; j++) {
            U8 pk; pk.u = *reinterpret_cast<const uint4*>(erow + k0 + j * 8);
            U8 po;
#pragma unroll
            for (int x = 0; x < 8; x++)
                po.h[x] = __float2bfloat16(__bfloat162float(pk.h[x]) * inv);
            *reinterpret_cast<uint4*>(Ps + tid * PITCH + j * 8) = po.u;
        }
        for (int i = tid; i < 384; i += 128) {
            int rr2 = i >> 3, ss = (i & 7) * 8;
            *reinterpret_cast<uint4*>(Vs + rr2 * PITCH + ss) =
                *reinterpret_cast<const uint4*>(
                    g_vt + ((size_t)bh * D_ + rr2) * T_ + k0 + ss);
        }
        __syncthreads();

#pragma unroll
        for (int ks = 0; ks < 4; ks++) {
            const int kb0 = ks * 16;
            uint32_t af[2][4];
#pragma unroll
            for (int mt = 0; mt < 2; mt++)
                ldsm_x4(af[mt], Ps + (wid * 32 + mt * 16 + aRow) * PITCH + kb0 + aKo);
            uint32_t bfr[6][2];
#pragma unroll
            for (int np = 0; np < 3; np++) {
                uint32_t bq[4];
                ldsm_x4(bq, Vs + (np * 16 + bRow) * PITCH + kb0 + bKo);
                bfr[np * 2][0] = bq[0]; bfr[np * 2][1] = bq[1];
                bfr[np * 2 + 1][0] = bq[2]; bfr[np * 2 + 1][1] = bq[3];
            }
#pragma unroll
            for (int mt = 0; mt < 2; mt++)
#pragma unroll
                for (int nt = 0; nt < 6; nt++)
                    mma16816(acc[mt][nt], af[mt][0], af[mt][1], af[mt][2], af[mt][3],
                             bfr[nt][0], bfr[nt][1]);
        }
        __syncthreads();
    }

#pragma unroll
    for (int mt = 0; mt < 2; mt++) {
        int r0 = qt * 128 + wid * 32 + mt * 16 + (lane >> 2);
#pragma unroll
        for (int nt = 0; nt < 6; nt++) {
            int c0 = nt * 8 + (lane & 3) * 2;
#pragma unroll
            for (int half = 0; half < 2; half++) {
                int rr = r0 + half * 8;
                __nv_bfloat162 pk;
                pk.x = __float2bfloat16(acc[mt][nt][half * 2 + 0]);
                pk.y = __float2bfloat16(acc[mt][nt][half * 2 + 1]);
                *reinterpret_cast<__nv_bfloat162*>(
                    &g_y[(size_t)(b * T_ + rr) * C_ + h * D_ + c0]) = pk;
            }
        }
    }
}

// ---------------- launch ----------------
extern "C" void kernel_launch(void* const* d_in, const int* in_sizes, int n_in,
                              void* d_out, int out_size) {
    const void* x = nullptr; const void* w_attn = nullptr; const void* w_proj = nullptr;
    for (int i = 0; i < n_in; i++) {
        if      (in_sizes[i] == M_ * C_)  x      = d_in[i];
        else if (in_sizes[i] == C_ * C3_) w_attn = d_in[i];
        else if (in_sizes[i] == C_ * C_)  w_proj = d_in[i];
    }
    if (!x || !w_attn || !w_proj) { x = d_in[0]; w_attn = d_in[1]; w_proj = d_in[2]; }
    float* out = (float*)d_out;   // output dtype is float32

    __nv_bfloat16 *xb, *wat, *wpt, *qkv, *y;
    cudaGetSymbolAddress((void**)&xb,  g_xb);
    cudaGetSymbolAddress((void**)&wat, g_wat);
    cudaGetSymbolAddress((void**)&wpt, g_wpt);
    cudaGetSymbolAddress((void**)&qkv, g_qkv);
    cudaGetSymbolAddress((void**)&y,   g_y);

    const int nx = M_ * C_;

    detect_dtype3<<<3, 256>>>(x, w_attn, w_proj);

    cast_input4<<<(nx/4 + 255) / 256, 256>>>(x, xb, nx/4, 0);

    {
        dim3 blk(32, 8);
        dim3 g1(C3_ / 32, C_ / 32);
        transpose_cast<<<g1, blk>>>(w_attn, wat, C_, C3_, 1);
        dim3 g2(C_ / 32, C_ / 32);
        transpose_cast<<<g2, blk>>>(w_proj, wpt, C_, C_, 2);
    }

    // QKV = Xb @ Wattn
    {
        dim3 grid((C3_ + 127) / 128, M_ / 128);
        gemm_hmma<0><<<grid, 256>>>(xb, wat, qkv, M_, C3_, C_);
    }

    // V^T per head
    {
        dim3 grid(T_ / 64, BH_);
        vt_kernel<<<grid, 256>>>();
    }

    // QK logits (causal tiles) + per-tile row maxima (contention-free)
    {
        dim3 grid(T_ / 128, T_ / 128, BH_);
        qk_hmma<<<grid, 256>>>();
    }

    // softmax: one sweep, s -> e in place, lb per row
    {
        softmax_es<<<BHT / 4, 128>>>();
    }

    // O = P*V via HMMA -> g_y
    {
        dim3 grid(T_ / 128, BH_);
        pv_hmma<<<grid, 128>>>();
    }

    // out(f32) = bf16round( Y @ Wproj )
    {
        dim3 grid((C_ + 127) / 128, M_ / 128);
        gemm_hmma<1><<<grid, 256>>>(y, wpt, out, M_, C_, C_);
    }
}

// round 16
// speedup vs baseline: 1.6451x; 1.6451x over previous
#include <cuda_runtime.h>
#include <cuda_bf16.h>
#include <math.h>
#include <stdint.h>

#define B_  4
#define T_  2048
#define C_  672
#define H_  14
#define D_  48
#define C3_ 2016
#define M_  (B_*T_)    // 8192
#define BHT (B_*H_*T_) // 114688
#define BH_ (B_*H_)    // 56

// ---------------- scratch ----------------
__device__ __nv_bfloat16 g_xb [(size_t)M_*C_];
__device__ __nv_bfloat16 g_wat[(size_t)C3_*C_];    // w_attn^T
__device__ __nv_bfloat16 g_wpt[(size_t)C_*C_];     // w_proj^T
__device__ __nv_bfloat16 g_qkv[(size_t)M_*C3_];
__device__ __nv_bfloat16 g_vt [(size_t)BH_*D_*T_]; // V^T per head [bh][48][2048]
__device__ __nv_bfloat16 g_y  [(size_t)M_*C_];
__device__ __nv_bfloat16 g_s  [(size_t)BHT*T_];    // logits -> e (in place)
__device__ float         g_lb [(size_t)BHT];
__device__ int g_isbf16[3];

__device__ __forceinline__ float rbf(float v) {
    return __bfloat162float(__float2bfloat16(v));
}

__device__ __forceinline__ void mma16816(float c[4],
        uint32_t a0, uint32_t a1, uint32_t a2, uint32_t a3,
        uint32_t b0, uint32_t b1) {
    asm volatile(
        "mma.sync.aligned.m16n8k16.row.col.f32.bf16.bf16.f32 "
        "{%0,%1,%2,%3}, {%4,%5,%6,%7}, {%8,%9}, {%0,%1,%2,%3};\n"
        : "+f"(c[0]), "+f"(c[1]), "+f"(c[2]), "+f"(c[3])
        : "r"(a0), "r"(a1), "r"(a2), "r"(a3), "r"(b0), "r"(b1));
}

__device__ __forceinline__ void ldsm_x4(uint32_t r[4], const __nv_bfloat16* p) {
    uint32_t addr = (uint32_t)__cvta_generic_to_shared(p);
    asm volatile("ldmatrix.sync.aligned.m8n8.x4.shared.b16 {%0,%1,%2,%3}, [%4];"
                 : "=r"(r[0]), "=r"(r[1]), "=r"(r[2]), "=r"(r[3]) : "r"(addr));
}

// ---------------- input dtype detection (one launch, 3 blocks) --------------
__global__ void detect_dtype3(const void* b0, const void* b1, const void* b2) {
    __shared__ int cnt;
    if (threadIdx.x == 0) cnt = 0;
    __syncthreads();
    const void* bufs[3] = {b0, b1, b2};
    const __nv_bfloat16* hb = (const __nv_bfloat16*)bufs[blockIdx.x];
    int local = 0;
    for (int i = threadIdx.x; i < 4096; i += 256) {
        float v = fabsf(__bfloat162float(hb[i]));
        if (isfinite(v) && v > 1e-5f && v < 1e3f) local++;
    }
    atomicAdd(&cnt, local);
    __syncthreads();
    if (threadIdx.x == 0) g_isbf16[blockIdx.x] = (cnt > 3072);
}

__global__ void cast_input4(const void* src, __nv_bfloat16* dst, int n4, int which) {
    int i = blockIdx.x * blockDim.x + threadIdx.x;
    if (i >= n4) return;
    if (g_isbf16[which]) {
        reinterpret_cast<uint2*>(dst)[i] = reinterpret_cast<const uint2*>(src)[i];
    } else {
        float4 v = reinterpret_cast<const float4*>(src)[i];
        union { __nv_bfloat16 h[4]; uint2 u; } pk;
        pk.h[0] = __float2bfloat16(v.x);
        pk.h[1] = __float2bfloat16(v.y);
        pk.h[2] = __float2bfloat16(v.z);
        pk.h[3] = __float2bfloat16(v.w);
        reinterpret_cast<uint2*>(dst)[i] = pk.u;
    }
}

// ---------------- transpose + cast: src [R][C] (f32 or bf16) -> dst [C][R] bf16
__global__ void transpose_cast(const void* src, __nv_bfloat16* dst,
                               int R, int C, int which) {
    __shared__ __nv_bfloat16 tile[32][33];
    const bool isb = g_isbf16[which] != 0;
    int x = blockIdx.x * 32 + threadIdx.x;
#pragma unroll
    for (int j = 0; j < 4; j++) {
        int y = blockIdx.y * 32 + threadIdx.y + j * 8;
        if (y < R && x < C) {
            __nv_bfloat16 v = isb
                ? ((const __nv_bfloat16*)src)[(size_t)y * C + x]
                : __float2bfloat16(((const float*)src)[(size_t)y * C + x]);
            tile[threadIdx.y + j * 8][threadIdx.x] = v;
        }
    }
    __syncthreads();
    int tx = blockIdx.y * 32 + threadIdx.x;
#pragma unroll
    for (int j = 0; j < 4; j++) {
        int ty = blockIdx.x * 32 + threadIdx.y + j * 8;
        if (ty < C && tx < R) dst[(size_t)ty * R + tx] = tile[threadIdx.x][threadIdx.y + j * 8];
    }
}

// ---------------- HMMA GEMM: C = A[M][K] * Bt[N][K]^T ----------------
// cp.async double-buffered smem pipeline (1-deep lookahead).
template<int EPI>
__global__ __launch_bounds__(256)
void gemm_hmma(const __nv_bfloat16* __restrict__ A,
               const __nv_bfloat16* __restrict__ Bt,
               void* __restrict__ Cout,
               int M, int N, int K) {
    const int PITCH = 40;
    __shared__ __nv_bfloat16 As[2][128 * PITCH];
    __shared__ __nv_bfloat16 Bs[2][128 * PITCH];

    const int tid = threadIdx.x, lane = tid & 31, wid = tid >> 5;
    const int wm = wid >> 2, wn = wid & 3;
    const int rowC = blockIdx.y * 128;
    const int colC = blockIdx.x * 128;

    const int srow = tid >> 1;
    const int sseg = (tid & 1) * 16;
    const __nv_bfloat16* Ag = A  + (size_t)(rowC + srow) * K + sseg;
    const __nv_bfloat16* Bg = Bt + (size_t)(colC + srow) * K + sseg;
    const int bbytes = ((colC + srow) < N) ? 16 : 0;   // zero-fill OOB B rows

    float acc[4][4][4];
#pragma unroll
    for (int mt = 0; mt < 4; mt++)
#pragma unroll
        for (int nt = 0; nt < 4; nt++)
#pragma unroll
            for (int r = 0; r < 4; r++) acc[mt][nt][r] = 0.f;

    const int nit = K / 32;

    // per-thread smem targets (byte addresses for cp.async)
    uint32_t daBase0 = (uint32_t)__cvta_generic_to_shared(&As[0][srow * PITCH + sseg]);
    uint32_t daBase1 = (uint32_t)__cvta_generic_to_shared(&As[1][srow * PITCH + sseg]);
    uint32_t dbBase0 = (uint32_t)__cvta_generic_to_shared(&Bs[0][srow * PITCH + sseg]);
    uint32_t dbBase1 = (uint32_t)__cvta_generic_to_shared(&Bs[1][srow * PITCH + sseg]);

#define GEMM_ISSUE(IT, BUF)                                                        \
    do {                                                                           \
        uint32_t _da = (BUF) ? daBase1 : daBase0;                                  \
        uint32_t _db = (BUF) ? dbBase1 : dbBase0;                                  \
        const __nv_bfloat16* _sa = Ag + (IT) * 32;                                 \
        const __nv_bfloat16* _sb = Bg + (IT) * 32;                                 \
        asm volatile("cp.async.cg.shared.global [%0], [%1], 16;"                   \
                     :: "r"(_da), "l"(_sa));                                       \
        asm volatile("cp.async.cg.shared.global [%0], [%1], 16;"                   \
                     :: "r"(_da + 16), "l"(_sa + 8));                              \
        asm volatile("cp.async.cg.shared.global [%0], [%1], 16, %2;"               \
                     :: "r"(_db), "l"(_sb), "r"(bbytes));                          \
        asm volatile("cp.async.cg.shared.global [%0], [%1], 16, %2;"               \
                     :: "r"(_db + 16), "l"(_sb + 8), "r"(bbytes));                 \
        asm volatile("cp.async.commit_group;");                                    \
    } while (0)

    GEMM_ISSUE(0, 0);

    const int aRow = lane & 15, aKo = (lane >> 4) * 8;
    const int bRow = (lane & 7) + (lane >> 4) * 8;
    const int bKo  = ((lane >> 3) & 1) * 8;

    for (int it = 0; it < nit; it++) {
        const int cur = it & 1;
        if (it + 1 < nit) {
            GEMM_ISSUE(it + 1, cur ^ 1);
            asm volatile("cp.async.wait_group 1;");
        } else {
            asm volatile("cp.async.wait_group 0;");
        }
        __syncthreads();

        const __nv_bfloat16* Ab = As[cur];
        const __nv_bfloat16* Bb = Bs[cur];
#pragma unroll
        for (int ks = 0; ks < 2; ks++) {
            const int kb0 = ks * 16;
            uint32_t af[4][4];
#pragma unroll
            for (int mt = 0; mt < 4; mt++)
                ldsm_x4(af[mt], Ab + (wm * 64 + mt * 16 + aRow) * PITCH + kb0 + aKo);
            uint32_t bfr[4][2];
#pragma unroll
            for (int np = 0; np < 2; np++) {
                uint32_t bq[4];
                ldsm_x4(bq, Bb + (wn * 32 + np * 16 + bRow) * PITCH + kb0 + bKo);
                bfr[np * 2][0] = bq[0]; bfr[np * 2][1] = bq[1];
                bfr[np * 2 + 1][0] = bq[2]; bfr[np * 2 + 1][1] = bq[3];
            }
#pragma unroll
            for (int mt = 0; mt < 4; mt++)
#pragma unroll
                for (int nt = 0; nt < 4; nt++)
                    mma16816(acc[mt][nt], af[mt][0], af[mt][1], af[mt][2], af[mt][3],
                             bfr[nt][0], bfr[nt][1]);
        }
        __syncthreads();   // compute done before buffer refilled next iter
    }
#undef GEMM_ISSUE

#pragma unroll
    for (int mt = 0; mt < 4; mt++) {
        int r0 = rowC + wm * 64 + mt * 16 + (lane >> 2);
#pragma unroll
        for (int nt = 0; nt < 4; nt++) {
            int c0 = colC + wn * 32 + nt * 8 + (lane & 3) * 2;
            if (c0 >= N) continue;
            if (EPI == 0) {
                __nv_bfloat16* Cb = (__nv_bfloat16*)Cout;
                __nv_bfloat162 p0, p1;
                p0.x = __float2bfloat16(acc[mt][nt][0]);
                p0.y = __float2bfloat16(acc[mt][nt][1]);
                p1.x = __float2bfloat16(acc[mt][nt][2]);
                p1.y = __float2bfloat16(acc[mt][nt][3]);
                *reinterpret_cast<__nv_bfloat162*>(Cb + (size_t)r0 * N + c0)       = p0;
                *reinterpret_cast<__nv_bfloat162*>(Cb + (size_t)(r0 + 8) * N + c0) = p1;
            } else {
                float* Cf = (float*)Cout;
                float2 q0 = make_float2(rbf(acc[mt][nt][0]), rbf(acc[mt][nt][1]));
                float2 q1 = make_float2(rbf(acc[mt][nt][2]), rbf(acc[mt][nt][3]));
                *reinterpret_cast<float2*>(Cf + (size_t)r0 * N + c0)       = q0;
                *reinterpret_cast<float2*>(Cf + (size_t)(r0 + 8) * N + c0) = q1;
            }
        }
    }
}

// ---------------- V^T per head: g_vt[bh][d][t] ----------------
__global__ __launch_bounds__(256)
void vt_kernel() {
    int tt = blockIdx.x, bh = blockIdx.y;
    int b = bh / H_, h = bh % H_;
    __shared__ __nv_bfloat16 tile[64][56];
    for (int i = threadIdx.x; i < 64 * 6; i += 256) {
        int r = i / 6, s = (i % 6) * 8;
        *reinterpret_cast<uint4*>(&tile[r][s]) =
            *reinterpret_cast<const uint4*>(
                &g_qkv[(size_t)(b * T_ + tt * 64 + r) * C3_ + 2 * C_ + h * D_ + s]);
    }
    __syncthreads();
    for (int i = threadIdx.x; i < D_ * 64; i += 256) {
        int d = i / 64, t = i % 64;
        g_vt[((size_t)bh * D_ + d) * T_ + tt * 64 + t] = tile[t][d];
    }
}

// ---------------- QK logits via HMMA (reads g_qkv directly) ----------------
__global__ __launch_bounds__(256)
void qk_hmma() {
    int ct = blockIdx.x, rt = blockIdx.y, bh = blockIdx.z;
    if (ct > rt + 1) return;
    int b = bh / H_, h = bh % H_;
    const int PITCH = 56;
    __shared__ __nv_bfloat16 Qs[128 * PITCH];
    __shared__ __nv_bfloat16 Ks[128 * PITCH];

    const int tid = threadIdx.x, lane = tid & 31, wid = tid >> 5;
    const int wm = wid >> 2, wn = wid & 3;

    const __nv_bfloat16* Qg = g_qkv + (size_t)(b * T_ + rt * 128) * C3_ + h * D_;
    const __nv_bfloat16* Kg = g_qkv + (size_t)(b * T_ + ct * 128) * C3_ + C_ + h * D_;
    for (int c = tid; c < 768; c += 256) {
        int r = c / 6, s = (c % 6) * 8;
        *reinterpret_cast<uint4*>(Qs + r * PITCH + s) =
            *reinterpret_cast<const uint4*>(Qg + (size_t)r * C3_ + s);
        *reinterpret_cast<uint4*>(Ks + r * PITCH + s) =
            *reinterpret_cast<const uint4*>(Kg + (size_t)r * C3_ + s);
    }
    __syncthreads();

    float acc[4][4][4];
#pragma unroll
    for (int mt = 0; mt < 4; mt++)
#pragma unroll
        for (int nt = 0; nt < 4; nt++)
#pragma unroll
            for (int r = 0; r < 4; r++) acc[mt][nt][r] = 0.f;

    const int aRow = lane & 15, aKo = (lane >> 4) * 8;
    const int bRow = (lane & 7) + (lane >> 4) * 8;
    const int bKo  = ((lane >> 3) & 1) * 8;

#pragma unroll
    for (int ks = 0; ks < 3; ks++) {
        const int kb0 = ks * 16;
        uint32_t af[4][4];
#pragma unroll
        for (int mt = 0; mt < 4; mt++)
            ldsm_x4(af[mt], Qs + (wm * 64 + mt * 16 + aRow) * PITCH + kb0 + aKo);
        uint32_t bfr[4][2];
#pragma unroll
        for (int np = 0; np < 2; np++) {
            uint32_t bq[4];
            ldsm_x4(bq, Ks + (wn * 32 + np * 16 + bRow) * PITCH + kb0 + bKo);
            bfr[np * 2][0] = bq[0]; bfr[np * 2][1] = bq[1];
            bfr[np * 2 + 1][0] = bq[2]; bfr[np * 2 + 1][1] = bq[3];
        }
#pragma unroll
        for (int mt = 0; mt < 4; mt++)
#pragma unroll
            for (int nt = 0; nt < 4; nt++)
                mma16816(acc[mt][nt], af[mt][0], af[mt][1], af[mt][2], af[mt][3],
                         bfr[nt][0], bfr[nt][1]);
    }

    const float scale = rbf(0.14433756729740643f);
    const __nv_bfloat16 NEGINF = __float2bfloat16(-INFINITY);
#pragma unroll
    for (int mt = 0; mt < 4; mt++) {
        int r0 = rt * 128 + wm * 64 + mt * 16 + (lane >> 2);
#pragma unroll
        for (int nt = 0; nt < 4; nt++) {
            int c0 = ct * 128 + wn * 32 + nt * 8 + (lane & 3) * 2;
#pragma unroll
            for (int half = 0; half < 2; half++) {
                int rr = r0 + half * 8;
                float rq = rbf((float)rr);
                __nv_bfloat162 pk;
                float v0 = acc[mt][nt][half * 2 + 0];
                float v1 = acc[mt][nt][half * 2 + 1];
                pk.x = (rbf((float)(c0    )) <= rq) ? __float2bfloat16(rbf(v0) * scale) : NEGINF;
                pk.y = (rbf((float)(c0 + 1)) <= rq) ? __float2bfloat16(rbf(v1) * scale) : NEGINF;
                *reinterpret_cast<__nv_bfloat162*>(
                    &g_s[((size_t)bh * T_ + rr) * T_ + c0]) = pk;
            }
        }
    }
}

// ---------------- softmax: warp per row; s -> e in place; lb out ------------
__global__ __launch_bounds__(128)
void softmax_es() {
    const int wid = threadIdx.x >> 5, lane = threadIdx.x & 31;
    const int r = blockIdx.x * 4 + wid;        // row over BHT
    const int t = r & (T_ - 1);
    const int qt = t >> 7;
    const int ncov = min(2 * qt + 3, 32);      // covered 64-key tiles
    const int nvec = ncov * 8;                 // uint4 count

    uint4* sv = reinterpret_cast<uint4*>(g_s + (size_t)r * T_);
    union U8 { uint4 u; __nv_bfloat16 h[8]; };

    float m = -1e30f;
    for (int i = lane; i < nvec; i += 32) {
        U8 pk; pk.u = sv[i];
#pragma unroll
        for (int j = 0; j < 8; j++) m = fmaxf(m, __bfloat162float(pk.h[j]));
    }
#pragma unroll
    for (int off = 16; off; off >>= 1)
        m = fmaxf(m, __shfl_xor_sync(0xffffffffu, m, off));

    float l = 0.f;
    for (int i = lane; i < nvec; i += 32) {
        U8 pk; pk.u = sv[i];
        U8 eo;
#pragma unroll
        for (int j = 0; j < 8; j++) {
            float s = __bfloat162float(pk.h[j]);
            float e = rbf(__expf(rbf(s - m)));
            l += e;
            eo.h[j] = __float2bfloat16(e);
        }
        sv[i] = eo.u;
    }
#pragma unroll
    for (int off = 16; off; off >>= 1)
        l += __shfl_xor_sync(0xffffffffu, l, off);

    if (lane == 0) g_lb[r] = rbf(l);
}

// ---------------- PV via HMMA: O[128 x 48] = P * V per (qt, bh) -------------
__global__ __launch_bounds__(128)
void pv_hmma() {
    const int qt = blockIdx.x, bh = blockIdx.y;
    const int b = bh / H_, h = bh % H_;
    const int PITCH = 72;                 // 64 k + pad
    __shared__ __nv_bfloat16 Ps[128 * PITCH];
    __shared__ __nv_bfloat16 Vs[48 * PITCH];

    const int tid = threadIdx.x, lane = tid & 31, wid = tid >> 5;
    const int rowg = qt * 128 + tid;
    const float inv = 1.0f / g_lb[(size_t)bh * T_ + rowg];
    const __nv_bfloat16* erow = g_s + ((size_t)bh * T_ + rowg) * T_;

    float acc[2][6][4];
#pragma unroll
    for (int mt = 0; mt < 2; mt++)
#pragma unroll
        for (int nt = 0; nt < 6; nt++)
#pragma unroll
            for (int q = 0; q < 4; q++) acc[mt][nt][q] = 0.f;

    const int ncov = min(2 * qt + 3, 32);   // 64-key chunks (= softmax coverage)
    union U8 { uint4 u; __nv_bfloat16 h[8]; };

    const int aRow = lane & 15, aKo = (lane >> 4) * 8;
    const int bRow = (lane & 7) + (lane >> 4) * 8;
    const int bKo  = ((lane >> 3) & 1) * 8;

    for (int it = 0; it < ncov; it++) {
        const int k0 = it * 64;
#pragma unroll
        for (int j = 0; j < 8; j++) {
            U8 pk; pk.u = *reinterpret_cast<const uint4*>(erow + k0 + j * 8);
            U8 po;
#pragma unroll
            for (int x = 0; x < 8; x++)
                po.h[x] = __float2bfloat16(__bfloat162float(pk.h[x]) * inv);
            *reinterpret_cast<uint4*>(Ps + tid * PITCH + j * 8) = po.u;
        }
        for (int i = tid; i < 384; i += 128) {
            int rr2 = i >> 3, ss = (i & 7) * 8;
            *reinterpret_cast<uint4*>(Vs + rr2 * PITCH + ss) =
                *reinterpret_cast<const uint4*>(
                    g_vt + ((size_t)bh * D_ + rr2) * T_ + k0 + ss);
        }
        __syncthreads();

#pragma unroll
        for (int ks = 0; ks < 4; ks++) {
            const int kb0 = ks * 16;
            uint32_t af[2][4];
#pragma unroll
            for (int mt = 0; mt < 2; mt++)
                ldsm_x4(af[mt], Ps + (wid * 32 + mt * 16 + aRow) * PITCH + kb0 + aKo);
            uint32_t bfr[6][2];
#pragma unroll
            for (int np = 0; np < 3; np++) {
                uint32_t bq[4];
                ldsm_x4(bq, Vs + (np * 16 + bRow) * PITCH + kb0 + bKo);
                bfr[np * 2][0] = bq[0]; bfr[np * 2][1] = bq[1];
                bfr[np * 2 + 1][0] = bq[2]; bfr[np * 2 + 1][1] = bq[3];
            }
#pragma unroll
            for (int mt = 0; mt < 2; mt++)
#pragma unroll
                for (int nt = 0; nt < 6; nt++)
                    mma16816(acc[mt][nt], af[mt][0], af[mt][1], af[mt][2], af[mt][3],
                             bfr[nt][0], bfr[nt][1]);
        }
        __syncthreads();
    }

#pragma unroll
    for (int mt = 0; mt < 2; mt++) {
        int r0 = qt * 128 + wid * 32 + mt * 16 + (lane >> 2);
#pragma unroll
        for (int nt = 0; nt < 6; nt++) {
            int c0 = nt * 8 + (lane & 3) * 2;
#pragma unroll
            for (int half = 0; half < 2; half++) {
                int rr = r0 + half * 8;
                __nv_bfloat162 pk;
                pk.x = __float2bfloat16(acc[mt][nt][half * 2 + 0]);
                pk.y = __float2bfloat16(acc[mt][nt][half * 2 + 1]);
                *reinterpret_cast<__nv_bfloat162*>(
                    &g_y[(size_t)(b * T_ + rr) * C_ + h * D_ + c0]) = pk;
            }
        }
    }
}

// ---------------- launch ----------------
extern "C" void kernel_launch(void* const* d_in, const int* in_sizes, int n_in,
                              void* d_out, int out_size) {
    const void* x = nullptr; const void* w_attn = nullptr; const void* w_proj = nullptr;
    for (int i = 0; i < n_in; i++) {
        if      (in_sizes[i] == M_ * C_)  x      = d_in[i];
        else if (in_sizes[i] == C_ * C3_) w_attn = d_in[i];
        else if (in_sizes[i] == C_ * C_)  w_proj = d_in[i];
    }
    if (!x || !w_attn || !w_proj) { x = d_in[0]; w_attn = d_in[1]; w_proj = d_in[2]; }
    float* out = (float*)d_out;   // output dtype is float32

    __nv_bfloat16 *xb, *wat, *wpt, *qkv, *y;
    cudaGetSymbolAddress((void**)&xb,  g_xb);
    cudaGetSymbolAddress((void**)&wat, g_wat);
    cudaGetSymbolAddress((void**)&wpt, g_wpt);
    cudaGetSymbolAddress((void**)&qkv, g_qkv);
    cudaGetSymbolAddress((void**)&y,   g_y);

    const int nx = M_ * C_;

    detect_dtype3<<<3, 256>>>(x, w_attn, w_proj);

    cast_input4<<<(nx/4 + 255) / 256, 256>>>(x, xb, nx/4, 0);

    {
        dim3 blk(32, 8);
        dim3 g1(C3_ / 32, C_ / 32);
        transpose_cast<<<g1, blk>>>(w_attn, wat, C_, C3_, 1);
        dim3 g2(C_ / 32, C_ / 32);
        transpose_cast<<<g2, blk>>>(w_proj, wpt, C_, C_, 2);
    }

    // QKV = Xb @ Wattn
    {
        dim3 grid((C3_ + 127) / 128, M_ / 128);
        gemm_hmma<0><<<grid, 256>>>(xb, wat, qkv, M_, C3_, C_);
    }

    // V^T per head
    {
        dim3 grid(T_ / 64, BH_);
        vt_kernel<<<grid, 256>>>();
    }

    // QK logits (causal tiles)
    {
        dim3 grid(T_ / 128, T_ / 128, BH_);
        qk_hmma<<<grid, 256>>>();
    }

    // softmax: two sweeps (max, then e/l), s -> e in place
    {
        softmax_es<<<BHT / 4, 128>>>();
    }

    // O = P*V via HMMA -> g_y
    {
        dim3 grid(T_ / 128, BH_);
        pv_hmma<<<grid, 128>>>();
    }

    // out(f32) = bf16round( Y @ Wproj )
    {
        dim3 grid((C_ + 127) / 128, M_ / 128);
        gemm_hmma<1><<<grid, 256>>>(y, wpt, out, M_, C_, C_);
    }
}